// round 9
// baseline (speedup 1.0000x reference)
#include <cuda_runtime.h>
#include <cuda_bf16.h>
#include <cstdint>

// FocalLoss: input [N,C]=[1048576,80] fp32, target [N] int32, gamma=2.
// out = mean_n sum_c -(1-pt)^2*logpt, pt = sigmoid(sign*x).
//
// R9: packed f32x2 math (Blackwell) in the streaming loop. Per float4, the
// (x,y)/(z,w) halves are processed as b64 packed lanes: MUL2/ADD2/FMA2 for
// scale, d, Newton reciprocal, p, p^2, accumulate. EX2/LG2 stay scalar MUFU
// (2/elem). Target fix-up per tile via L2-hit gather (same warp streamed the
// lines). loss(x)/ln2 = (g/(1+g))^2*log2(1+g), g=e^{-x}.

#define N_ROWS   1048576
#define C_CLS    80
#define ROWS_PER_TILE 32
#define F4_PER_TILE   640
#define N_TILES  (N_ROWS / ROWS_PER_TILE)   // 32768
#define NBLOCKS  1184              // 148 SMs * 8 CTAs, single wave
#define NTHREADS 256
#define WARPS_PER_BLOCK (NTHREADS / 32)
#define L2E      1.44269504f
#define LN2      0.6931471805599453

__device__ double g_partials[NBLOCKS];
__device__ unsigned int g_count;

typedef unsigned long long u64;

__device__ __forceinline__ float ex2f_(float x) {
    float y; asm("ex2.approx.f32 %0, %1;" : "=f"(y) : "f"(x)); return y;
}
__device__ __forceinline__ float lg2f_(float x) {
    float y; asm("lg2.approx.f32 %0, %1;" : "=f"(y) : "f"(x)); return y;
}
__device__ __forceinline__ u64 pk2(float lo, float hi) {
    u64 r; asm("mov.b64 %0, {%1, %2};" : "=l"(r) : "f"(lo), "f"(hi)); return r;
}
__device__ __forceinline__ void upk2(float& lo, float& hi, u64 v) {
    asm("mov.b64 {%0, %1}, %2;" : "=f"(lo), "=f"(hi) : "l"(v));
}
__device__ __forceinline__ u64 mul2(u64 a, u64 b) {
    u64 r; asm("mul.rn.f32x2 %0, %1, %2;" : "=l"(r) : "l"(a), "l"(b)); return r;
}
__device__ __forceinline__ u64 add2(u64 a, u64 b) {
    u64 r; asm("add.rn.f32x2 %0, %1, %2;" : "=l"(r) : "l"(a), "l"(b)); return r;
}
__device__ __forceinline__ u64 fma2(u64 a, u64 b, u64 c) {
    u64 r; asm("fma.rn.f32x2 %0, %1, %2, %3;" : "=l"(r) : "l"(a), "l"(b), "l"(c)); return r;
}

#define C2(x) ((((u64)(x)) << 32) | (u64)(x))
__device__ __forceinline__ u64 cpk(float f) {
    unsigned u = __float_as_uint(f);
    return C2(u);
}

// packed: acc += core(w0), core(w1) where w = v*log2e (non-target logit form)
__device__ __forceinline__ void focal2(u64 w01, u64& acc,
                                       u64 kONE, u64 kTWO, u64 kM1) {
    float w0, w1; upk2(w0, w1, w01);
    float g0 = ex2f_(w0);
    float g1 = ex2f_(w1);
    u64 g = pk2(g0, g1);
    u64 d = add2(g, kONE);
    float d0, d1; upk2(d0, d1, d);
    unsigned s0 = 0x7EF311C3u - __float_as_uint(d0);
    unsigned s1 = 0x7EF311C3u - __float_as_uint(d1);
    u64 r = ((u64)s1 << 32) | (u64)s0;
    // Newton x2: r = r * (2 - d*r)
    u64 m = mul2(d, r);
    r = mul2(r, fma2(m, kM1, kTWO));
    m = mul2(d, r);
    r = mul2(r, fma2(m, kM1, kTWO));
    u64 p  = mul2(g, r);                 // sigma(-x)
    u64 L  = pk2(lg2f_(d0), lg2f_(d1));  // log2(1+g)
    acc = fma2(mul2(p, p), L, acc);
}

// scalar core for the correction path
__device__ __forceinline__ float focal_core(float w) {
    float g = ex2f_(w);
    float d = 1.0f + g;
    float r = __uint_as_float(0x7EF311C3u - __float_as_uint(d));
    r = r * fmaf(-d, r, 2.0f);
    r = r * fmaf(-d, r, 2.0f);
    float p = g * r;
    return (p * p) * lg2f_(d);
}

__global__ __launch_bounds__(NTHREADS, 8) void focal_fused_kernel(
    const float* __restrict__ inp,
    const int* __restrict__ tgt,
    float* __restrict__ out)
{
    const unsigned lane   = threadIdx.x & 31u;
    const unsigned gwarp  = blockIdx.x * WARPS_PER_BLOCK + (threadIdx.x >> 5);
    const unsigned nwarps = gridDim.x * WARPS_PER_BLOCK;

    const float4* __restrict__ inp4 = (const float4*)inp;

    const u64 kONE = cpk(1.0f);
    const u64 kTWO = cpk(2.0f);
    const u64 kM1  = cpk(-1.0f);
    const u64 kL2E = cpk(L2E);

    u64 acc_a = 0ull, acc_b = 0ull;   // packed zero pairs
    float fcorr = 0.0f;

    for (unsigned tile = gwarp; tile < (unsigned)N_TILES; tile += nwarps) {
        const unsigned row0 = tile * ROWS_PER_TILE;
        const unsigned base = tile * (unsigned)F4_PER_TILE + lane;

        #pragma unroll 4
        for (unsigned k = 0; k < 20u; k++) {
            float4 v = __ldg(&inp4[base + k * 32u]);
            u64 w01 = mul2(pk2(v.x, v.y), kL2E);
            u64 w23 = mul2(pk2(v.z, v.w), kL2E);
            focal2(w01, acc_a, kONE, kTWO, kM1);
            focal2(w23, acc_b, kONE, kTWO, kM1);
        }

        // correction: lane fixes row (row0+lane); lines are L2-resident
        int   t  = __ldg(&tgt[row0 + lane]);
        float tv = __ldg(&inp[(row0 + lane) * (unsigned)C_CLS + (unsigned)t]);
        fcorr += focal_core(tv * -L2E) - focal_core(tv * L2E);
    }

    float a0, a1, b0, b1;
    upk2(a0, a1, acc_a);
    upk2(b0, b1, acc_b);
    float fsum = ((a0 + a1) + (b0 + b1)) + fcorr;

    #pragma unroll
    for (int off = 16; off > 0; off >>= 1)
        fsum += __shfl_down_sync(0xFFFFFFFFu, fsum, off);

    __shared__ double s_warp[WARPS_PER_BLOCK];
    int wid = threadIdx.x >> 5;
    if (lane == 0) s_warp[wid] = (double)fsum;
    __syncthreads();

    __shared__ bool s_last;
    if (threadIdx.x == 0) {
        double bsum = 0.0;
        #pragma unroll
        for (int w = 0; w < WARPS_PER_BLOCK; w++) bsum += s_warp[w];
        g_partials[blockIdx.x] = bsum;
        __threadfence();
        unsigned done = atomicAdd(&g_count, 1u);
        s_last = (done == gridDim.x - 1);
    }
    __syncthreads();

    if (s_last) {
        __threadfence();
        __shared__ double s_red[NTHREADS];
        double v = 0.0;
        for (int k = threadIdx.x; k < NBLOCKS; k += NTHREADS)
            v += g_partials[k];
        s_red[threadIdx.x] = v;
        __syncthreads();
        #pragma unroll
        for (int off = NTHREADS / 2; off > 0; off >>= 1) {
            if (threadIdx.x < off) s_red[threadIdx.x] += s_red[threadIdx.x + off];
            __syncthreads();
        }
        if (threadIdx.x == 0) {
            out[0] = (float)(s_red[0] * LN2 / (double)N_ROWS);
            g_count = 0;
        }
    }
}

extern "C" void kernel_launch(void* const* d_in, const int* in_sizes, int n_in,
                              void* d_out, int out_size)
{
    const float* inp = (const float*)d_in[0];
    const int* tgt   = (const int*)d_in[1];
    float* out       = (float*)d_out;

    focal_fused_kernel<<<NBLOCKS, NTHREADS>>>(inp, tgt, out);
}

// round 10
// speedup vs baseline: 1.1658x; 1.1658x over previous
#include <cuda_runtime.h>
#include <cuda_bf16.h>

// FocalLoss: input [N,C]=[1048576,80] fp32, target [N] int32, gamma=2.
// out = mean_n sum_c -(1-pt)^2*logpt, pt = sigmoid(sign*x).
//
// R10 = R8 (best: 63.9us) with the 2-step Newton reciprocal replaced by a
// single Halley step (3 FMAs, cubic: 5% seed err -> ~1.4e-4, oscillating
// sign -> cancels in the mean; gate is 1e-3).
// Streaming main loop (no target logic); per-tile correction via L2-hit
// gather by the same warp that streamed the lines.
// loss(x)/ln2 = (g/(1+g))^2*log2(1+g), g=e^{-x}; non-target: g=ex2(v*log2e).

#define N_ROWS   1048576
#define C_CLS    80
#define ROWS_PER_TILE 32
#define F4_PER_TILE   640          // 32 rows * 20 float4
#define N_TILES  (N_ROWS / ROWS_PER_TILE)   // 32768
#define NBLOCKS  1184              // 148 SMs * 8 CTAs, single wave at regs<=32
#define NTHREADS 256
#define WARPS_PER_BLOCK (NTHREADS / 32)
#define L2E      1.44269504f
#define LN2      0.6931471805599453

__device__ double g_partials[NBLOCKS];
__device__ unsigned int g_count;

__device__ __forceinline__ float ex2f_(float x) {
    float y; asm("ex2.approx.f32 %0, %1;" : "=f"(y) : "f"(x)); return y;
}
__device__ __forceinline__ float lg2f_(float x) {
    float y; asm("lg2.approx.f32 %0, %1;" : "=f"(y) : "f"(x)); return y;
}

// core(w) = (g/(1+g))^2 * log2(1+g) with g = 2^w.
// Non-target element v: w = v*L2E. Target element v: w = -v*L2E.
__device__ __forceinline__ float focal_core(float w) {
    float g = ex2f_(w);                                           // MUFU
    float d = 1.0f + g;                                           // FADD
    float r = __uint_as_float(0x7EF311C3u - __float_as_uint(d));  // IADD (alu)
    // Halley (cubic): e = 1 - d*r; r = r + r*(e + e^2)
    float e  = fmaf(-d, r, 1.0f);                                 // FFMA
    float e2 = fmaf(e, e, e);                                     // FFMA
    r = fmaf(r, e2, r);                                           // FFMA
    float p = g * r;                                              // FMUL: sigma(-x)
    return (p * p) * lg2f_(d);                                    // FMUL+MUFU+(folds to FFMA w/ acc)
}

__global__ __launch_bounds__(NTHREADS, 8) void focal_fused_kernel(
    const float* __restrict__ inp,
    const int* __restrict__ tgt,
    float* __restrict__ out)
{
    const unsigned lane   = threadIdx.x & 31u;
    const unsigned gwarp  = blockIdx.x * WARPS_PER_BLOCK + (threadIdx.x >> 5);
    const unsigned nwarps = gridDim.x * WARPS_PER_BLOCK;   // 9472

    const float4* __restrict__ inp4 = (const float4*)inp;

    float fs0 = 0.0f, fs1 = 0.0f;

    for (unsigned tile = gwarp; tile < (unsigned)N_TILES; tile += nwarps) {
        const unsigned row0 = tile * ROWS_PER_TILE;
        const unsigned base = tile * (unsigned)F4_PER_TILE + lane;

        // Main: stream 640 float4s, everything treated as non-target.
        #pragma unroll 4
        for (unsigned k = 0; k < 20u; k++) {
            float4 v = __ldg(&inp4[base + k * 32u]);
            fs0 += focal_core(v.x * L2E);
            fs1 += focal_core(v.y * L2E);
            fs0 += focal_core(v.z * L2E);
            fs1 += focal_core(v.w * L2E);
        }

        // Correction: lane fixes row (row0+lane). Lines just streamed -> L2 hit.
        int   t  = __ldg(&tgt[row0 + lane]);
        float tv = __ldg(&inp[(row0 + lane) * (unsigned)C_CLS + (unsigned)t]);
        fs0 += focal_core(tv * -L2E) - focal_core(tv * L2E);
    }

    float fsum = fs0 + fs1;

    #pragma unroll
    for (int off = 16; off > 0; off >>= 1)
        fsum += __shfl_down_sync(0xFFFFFFFFu, fsum, off);

    __shared__ double s_warp[WARPS_PER_BLOCK];
    int wid = threadIdx.x >> 5;
    if (lane == 0) s_warp[wid] = (double)fsum;
    __syncthreads();

    __shared__ bool s_last;
    if (threadIdx.x == 0) {
        double bsum = 0.0;
        #pragma unroll
        for (int w = 0; w < WARPS_PER_BLOCK; w++) bsum += s_warp[w];
        g_partials[blockIdx.x] = bsum;
        __threadfence();
        unsigned done = atomicAdd(&g_count, 1u);
        s_last = (done == gridDim.x - 1);
    }
    __syncthreads();

    if (s_last) {
        __threadfence();
        __shared__ double s_red[NTHREADS];
        double v = 0.0;
        for (int k = threadIdx.x; k < NBLOCKS; k += NTHREADS)
            v += g_partials[k];
        s_red[threadIdx.x] = v;
        __syncthreads();
        #pragma unroll
        for (int off = NTHREADS / 2; off > 0; off >>= 1) {
            if (threadIdx.x < off) s_red[threadIdx.x] += s_red[threadIdx.x + off];
            __syncthreads();
        }
        if (threadIdx.x == 0) {
            out[0] = (float)(s_red[0] * LN2 / (double)N_ROWS);
            g_count = 0;
        }
    }
}

extern "C" void kernel_launch(void* const* d_in, const int* in_sizes, int n_in,
                              void* d_out, int out_size)
{
    const float* inp = (const float*)d_in[0];
    const int* tgt   = (const int*)d_in[1];
    float* out       = (float*)d_out;

    focal_fused_kernel<<<NBLOCKS, NTHREADS>>>(inp, tgt, out);
}

// round 11
// speedup vs baseline: 1.2272x; 1.0527x over previous
#include <cuda_runtime.h>
#include <cuda_bf16.h>

// FocalLoss: input [N,C]=[1048576,80] fp32, target [N] int32, gamma=2.
// out = mean_n sum_c -(1-pt)^2*logpt, pt = sigmoid(sign*x).
//
// R11 = R10 (63.3us) +
//  (a) software-pipelined target correction: tgt load at tile start, the
//      dependent gather mid-stream, math at tile end (hides ~2x L2 latency
//      per tile that was previously exposed at the tail);
//  (b) p = 1 - r formulation: sigma(-x) = 1 - 1/(1+g); p^2 = fma(r, r-2, 1),
//      shortening the post-reciprocal dependency chain.
// loss(x)/ln2 = (1-1/(1+g))^2 * log2(1+g), g = e^{-x} = ex2(v*log2e) for
// non-target elements; target uses w = -v*log2e. Halley-refined magic
// reciprocal (err ~1.4e-4, sign-oscillating -> cancels in the mean).

#define N_ROWS   1048576
#define C_CLS    80
#define ROWS_PER_TILE 32
#define F4_PER_TILE   640          // 32 rows * 20 float4
#define N_TILES  (N_ROWS / ROWS_PER_TILE)   // 32768
#define NBLOCKS  1184              // 148 SMs * 8 CTAs, single wave at regs<=32
#define NTHREADS 256
#define WARPS_PER_BLOCK (NTHREADS / 32)
#define L2E      1.44269504f
#define LN2      0.6931471805599453

__device__ double g_partials[NBLOCKS];
__device__ unsigned int g_count;

__device__ __forceinline__ float ex2f_(float x) {
    float y; asm("ex2.approx.f32 %0, %1;" : "=f"(y) : "f"(x)); return y;
}
__device__ __forceinline__ float lg2f_(float x) {
    float y; asm("lg2.approx.f32 %0, %1;" : "=f"(y) : "f"(x)); return y;
}

// core(w) = (1 - 1/(1+g))^2 * log2(1+g), g = 2^w.
__device__ __forceinline__ float focal_core(float w) {
    float g = ex2f_(w);                                           // MUFU
    float d = 1.0f + g;                                           // FADD
    float r = __uint_as_float(0x7EF311C3u - __float_as_uint(d));  // IADD (alu)
    // Halley (cubic): e = 1 - d*r; r += r*(e + e^2)
    float e  = fmaf(-d, r, 1.0f);
    float e2 = fmaf(e, e, e);
    r = fmaf(r, e2, r);
    float pp = fmaf(r, r - 2.0f, 1.0f);      // (1-r)^2
    return pp * lg2f_(d);                    // folds into FFMA with acc
}

__global__ __launch_bounds__(NTHREADS, 8) void focal_fused_kernel(
    const float* __restrict__ inp,
    const int* __restrict__ tgt,
    float* __restrict__ out)
{
    const unsigned lane   = threadIdx.x & 31u;
    const unsigned gwarp  = blockIdx.x * WARPS_PER_BLOCK + (threadIdx.x >> 5);
    const unsigned nwarps = gridDim.x * WARPS_PER_BLOCK;   // 9472

    const float4* __restrict__ inp4 = (const float4*)inp;

    float fs0 = 0.0f, fs1 = 0.0f;

    for (unsigned tile = gwarp; tile < (unsigned)N_TILES; tile += nwarps) {
        const unsigned row0 = tile * ROWS_PER_TILE;
        const unsigned base = tile * (unsigned)F4_PER_TILE + lane;

        // pipeline stage 1: issue target-index load early
        int t = __ldg(&tgt[row0 + lane]);

        float tv;
        #pragma unroll 4
        for (unsigned k = 0; k < 10u; k++) {
            float4 v = __ldg(&inp4[base + k * 32u]);
            fs0 += focal_core(v.x * L2E);
            fs1 += focal_core(v.y * L2E);
            fs0 += focal_core(v.z * L2E);
            fs1 += focal_core(v.w * L2E);
        }

        // pipeline stage 2: t has landed; issue the dependent gather now so it
        // completes under the second half of the stream (L2-resident line).
        tv = __ldg(&inp[(row0 + lane) * (unsigned)C_CLS + (unsigned)t]);

        #pragma unroll 4
        for (unsigned k = 10u; k < 20u; k++) {
            float4 v = __ldg(&inp4[base + k * 32u]);
            fs0 += focal_core(v.x * L2E);
            fs1 += focal_core(v.y * L2E);
            fs0 += focal_core(v.z * L2E);
            fs1 += focal_core(v.w * L2E);
        }

        // pipeline stage 3: correction math only (loads already landed)
        fs0 += focal_core(tv * -L2E) - focal_core(tv * L2E);
    }

    float fsum = fs0 + fs1;

    #pragma unroll
    for (int off = 16; off > 0; off >>= 1)
        fsum += __shfl_down_sync(0xFFFFFFFFu, fsum, off);

    __shared__ double s_warp[WARPS_PER_BLOCK];
    int wid = threadIdx.x >> 5;
    if (lane == 0) s_warp[wid] = (double)fsum;
    __syncthreads();

    __shared__ bool s_last;
    if (threadIdx.x == 0) {
        double bsum = 0.0;
        #pragma unroll
        for (int w = 0; w < WARPS_PER_BLOCK; w++) bsum += s_warp[w];
        g_partials[blockIdx.x] = bsum;
        __threadfence();
        unsigned done = atomicAdd(&g_count, 1u);
        s_last = (done == gridDim.x - 1);
    }
    __syncthreads();

    if (s_last) {
        __threadfence();
        __shared__ double s_red[NTHREADS];
        double v = 0.0;
        for (int k = threadIdx.x; k < NBLOCKS; k += NTHREADS)
            v += g_partials[k];
        s_red[threadIdx.x] = v;
        __syncthreads();
        #pragma unroll
        for (int off = NTHREADS / 2; off > 0; off >>= 1) {
            if (threadIdx.x < off) s_red[threadIdx.x] += s_red[threadIdx.x + off];
            __syncthreads();
        }
        if (threadIdx.x == 0) {
            out[0] = (float)(s_red[0] * LN2 / (double)N_ROWS);
            g_count = 0;
        }
    }
}

extern "C" void kernel_launch(void* const* d_in, const int* in_sizes, int n_in,
                              void* d_out, int out_size)
{
    const float* inp = (const float*)d_in[0];
    const int* tgt   = (const int*)d_in[1];
    float* out       = (float*)d_out;

    focal_fused_kernel<<<NBLOCKS, NTHREADS>>>(inp, tgt, out);
}

// round 12
// speedup vs baseline: 1.2325x; 1.0043x over previous
#include <cuda_runtime.h>
#include <cuda_bf16.h>

// FocalLoss: input [N,C]=[1048576,80] fp32, target [N] int32, gamma=2.
// out = mean_n sum_c -(1-pt)^2*logpt, pt = sigmoid(sign*x).
//
// R12 = R11 (60.1us) with the work quantum halved to kill the tail:
// 16-row tiles -> 65536 tiles / 9472 warps = 6.92 tiles/warp (max 7) vs the
// old 3.46 (max 4, i.e. 16% straggler tail). Correction predicated to lanes
// 0-15. Same pipelined gather, Halley reciprocal, single-wave 1184x256 grid.

#define N_ROWS   1048576
#define C_CLS    80
#define ROWS_PER_TILE 16
#define F4_PER_TILE   320          // 16 rows * 20 float4
#define N_TILES  (N_ROWS / ROWS_PER_TILE)   // 65536
#define NBLOCKS  1184              // 148 SMs * 8 CTAs, single wave at regs<=32
#define NTHREADS 256
#define WARPS_PER_BLOCK (NTHREADS / 32)
#define L2E      1.44269504f
#define LN2      0.6931471805599453

__device__ double g_partials[NBLOCKS];
__device__ unsigned int g_count;

__device__ __forceinline__ float ex2f_(float x) {
    float y; asm("ex2.approx.f32 %0, %1;" : "=f"(y) : "f"(x)); return y;
}
__device__ __forceinline__ float lg2f_(float x) {
    float y; asm("lg2.approx.f32 %0, %1;" : "=f"(y) : "f"(x)); return y;
}

// core(w) = (1 - 1/(1+g))^2 * log2(1+g), g = 2^w.
__device__ __forceinline__ float focal_core(float w) {
    float g = ex2f_(w);                                           // MUFU
    float d = 1.0f + g;                                           // FADD
    float r = __uint_as_float(0x7EF311C3u - __float_as_uint(d));  // IADD (alu)
    // Halley (cubic): e = 1 - d*r; r += r*(e + e^2)
    float e  = fmaf(-d, r, 1.0f);
    float e2 = fmaf(e, e, e);
    r = fmaf(r, e2, r);
    float pp = fmaf(r, r - 2.0f, 1.0f);      // (1-r)^2
    return pp * lg2f_(d);                    // folds into FFMA with acc
}

__global__ __launch_bounds__(NTHREADS, 8) void focal_fused_kernel(
    const float* __restrict__ inp,
    const int* __restrict__ tgt,
    float* __restrict__ out)
{
    const unsigned lane   = threadIdx.x & 31u;
    const unsigned gwarp  = blockIdx.x * WARPS_PER_BLOCK + (threadIdx.x >> 5);
    const unsigned nwarps = gridDim.x * WARPS_PER_BLOCK;   // 9472

    const float4* __restrict__ inp4 = (const float4*)inp;

    float fs0 = 0.0f, fs1 = 0.0f;

    for (unsigned tile = gwarp; tile < (unsigned)N_TILES; tile += nwarps) {
        const unsigned row0 = tile * ROWS_PER_TILE;
        const unsigned base = tile * (unsigned)F4_PER_TILE + lane;

        // stage 1: issue target-index load early (lanes 0-15 own one row each)
        int t = 0;
        if (lane < 16u) t = __ldg(&tgt[row0 + lane]);

        #pragma unroll 5
        for (unsigned k = 0; k < 5u; k++) {
            float4 v = __ldg(&inp4[base + k * 32u]);
            fs0 += focal_core(v.x * L2E);
            fs1 += focal_core(v.y * L2E);
            fs0 += focal_core(v.z * L2E);
            fs1 += focal_core(v.w * L2E);
        }

        // stage 2: dependent gather; line is L2-resident (streamed just above)
        float tv = 0.0f;
        if (lane < 16u)
            tv = __ldg(&inp[(row0 + lane) * (unsigned)C_CLS + (unsigned)t]);

        #pragma unroll 5
        for (unsigned k = 5u; k < 10u; k++) {
            float4 v = __ldg(&inp4[base + k * 32u]);
            fs0 += focal_core(v.x * L2E);
            fs1 += focal_core(v.y * L2E);
            fs0 += focal_core(v.z * L2E);
            fs1 += focal_core(v.w * L2E);
        }

        // stage 3: correction math (loads already landed)
        if (lane < 16u)
            fs0 += focal_core(tv * -L2E) - focal_core(tv * L2E);
    }

    float fsum = fs0 + fs1;

    #pragma unroll
    for (int off = 16; off > 0; off >>= 1)
        fsum += __shfl_down_sync(0xFFFFFFFFu, fsum, off);

    __shared__ double s_warp[WARPS_PER_BLOCK];
    int wid = threadIdx.x >> 5;
    if (lane == 0) s_warp[wid] = (double)fsum;
    __syncthreads();

    __shared__ bool s_last;
    if (threadIdx.x == 0) {
        double bsum = 0.0;
        #pragma unroll
        for (int w = 0; w < WARPS_PER_BLOCK; w++) bsum += s_warp[w];
        g_partials[blockIdx.x] = bsum;
        __threadfence();
        unsigned done = atomicAdd(&g_count, 1u);
        s_last = (done == gridDim.x - 1);
    }
    __syncthreads();

    if (s_last) {
        __threadfence();
        __shared__ double s_red[NTHREADS];
        double v = 0.0;
        for (int k = threadIdx.x; k < NBLOCKS; k += NTHREADS)
            v += g_partials[k];
        s_red[threadIdx.x] = v;
        __syncthreads();
        #pragma unroll
        for (int off = NTHREADS / 2; off > 0; off >>= 1) {
            if (threadIdx.x < off) s_red[threadIdx.x] += s_red[threadIdx.x + off];
            __syncthreads();
        }
        if (threadIdx.x == 0) {
            out[0] = (float)(s_red[0] * LN2 / (double)N_ROWS);
            g_count = 0;
        }
    }
}

extern "C" void kernel_launch(void* const* d_in, const int* in_sizes, int n_in,
                              void* d_out, int out_size)
{
    const float* inp = (const float*)d_in[0];
    const int* tgt   = (const int*)d_in[1];
    float* out       = (float*)d_out;

    focal_fused_kernel<<<NBLOCKS, NTHREADS>>>(inp, tgt, out);
}